// round 8
// baseline (speedup 1.0000x reference)
#include <cuda_runtime.h>
#include <cuda_bf16.h>

// ---------------- problem constants ----------------
#define BATCH 8
#define CH    256
#define HH    96
#define WW    96
#define HWSZ  (HH*WW)        // 9216
#define NWD   12             // windows per spatial dim
#define LWIN  144            // windows per image
#define NWIN  1152           // total windows (BATCH*LWIN)
#define QW    64             // queries per window (8x8)
#define NHEAD 8
#define HD    32
#define SCALE 0.1767766952966369f   // 32^-0.5

#define XW_ELEMS ((size_t)NWIN*QW*CH)   // 18,874,368

// ---------------- device scratch (no allocs allowed) ----------------
__device__ float g_xw[NWIN*QW*CH];        // [n][s][c]  window-gathered x
__device__ float g_q [NWIN*QW*CH];        // [n][s][o]  Q projection
__device__ float g_z [NWIN*QW*CH];        // attn out + rpe, BCHW-flat
__device__ float g_pool[NWIN*CH];         // pooled tokens [bl][c]
__device__ float g_poolpart[8*NWIN*CH];   // split-K partials
__device__ float g_kv[NWIN*2*CH];         // [bl][t*256 + head*32 + d]
__device__ float g_poolwT[CH*QW*CH];      // pool_w transposed to [o][s*256+c]

// ---------------- window gather: x(BCHW) -> g_xw[n][s][c] ----------------
__global__ __launch_bounds__(256) void k_gather(const float* __restrict__ x)
{
    __shared__ float tile[64][33];
    int n  = blockIdx.x;
    int ct = blockIdx.y;            // channel tile of 32
    int b  = n / LWIN;
    int wi = n % LWIN;
    int wh = wi / NWD, wwi = wi % NWD;
    int t = threadIdx.x;

    // load 32 channels x 64 window pixels; 8-consecutive-float reads (full 32B sectors)
    int c_loc = t >> 3;             // 0..31
    int j     = t & 7;              // 0..7
    const float* xb = x + ((size_t)b*CH + ct*32 + c_loc)*HWSZ + (wh*8)*WW + wwi*8 + j;
    #pragma unroll
    for (int i = 0; i < 8; i++)
        tile[i*8 + j][c_loc] = xb[i*WW];
    __syncthreads();

    // store coalesced over channels
    int c2 = t & 31;
    float* out = g_xw + (size_t)n*(QW*CH) + ct*32 + c2;
    #pragma unroll
    for (int it = 0; it < 8; it++) {
        int s = (t >> 5) + it*8;
        out[s*CH] = tile[s][c2];
    }
}

// ---------------- pool_w[o][c][s] -> g_poolwT[o][s*256+c] ----------------
__global__ __launch_bounds__(256) void k_poolwT(const float* __restrict__ pw)
{
    __shared__ float sm[128*65];
    int o  = blockIdx.x;
    int c0 = blockIdx.y * 128;
    int t  = threadIdx.x;
    const float* p = pw + (size_t)o*16384 + (size_t)c0*64;
    #pragma unroll 4
    for (int i = 0; i < 32; i++) {
        int idx = i*256 + t;
        int c = idx >> 6, s = idx & 63;
        sm[c*65 + s] = p[idx];
    }
    __syncthreads();
    float* out = g_poolwT + (size_t)o*16384 + c0;
    #pragma unroll 4
    for (int i = 0; i < 32; i++) {
        int idx = i*256 + t;
        int s = idx >> 7, c = idx & 127;
        out[s*256 + c] = sm[c*65 + s];
    }
}

// ---------------- split-K reduce for pool (+bias) ----------------
__global__ __launch_bounds__(256) void k_pool_reduce(const float* __restrict__ pb)
{
    int idx = blockIdx.x*256 + threadIdx.x;     // NWIN*CH
    float a = pb[idx & 255];
    #pragma unroll
    for (int z = 0; z < 8; z++)
        a += g_poolpart[(size_t)z*(NWIN*CH) + idx];
    g_pool[idx] = a;
}

// ---------------- tiled NT SGEMM: C[m,n] = sum_k A[m*K+k]*B[n*K+k] ----------------
// 64x64 tile, BK=16, 256 threads, 4x4 microtile. lda=ldb=K, ldc=N (exact tiles).
template<bool SPLIT, bool BIAS>
__global__ __launch_bounds__(256) void k_gemm(
    const float* __restrict__ A, const float* __restrict__ Bm,
    float* __restrict__ Cm, const float* __restrict__ bias,
    int M, int N, int K, int kcount)
{
    __shared__ float As[16][68];
    __shared__ float Bs[16][68];
    const int m0 = blockIdx.y * 64;
    const int n0 = blockIdx.x * 64;
    int k0 = 0;
    if (SPLIT) { k0 = blockIdx.z * kcount; Cm += (size_t)blockIdx.z * M * N; }
    const int tid = threadIdx.x;
    const int tx = tid & 15, ty = tid >> 4;
    const int lr = tid >> 2;           // 0..63 tile row
    const int lc = (tid & 3) * 4;      // k offset 0,4,8,12

    const float* Ap = A + (size_t)(m0 + lr)*K + k0 + lc;
    const float* Bp = Bm + (size_t)(n0 + lr)*K + k0 + lc;

    float acc[4][4] = {};
    for (int kt = 0; kt < kcount; kt += 16) {
        float4 av = *(const float4*)Ap;
        float4 bv = *(const float4*)Bp;
        __syncthreads();
        As[lc+0][lr] = av.x; As[lc+1][lr] = av.y; As[lc+2][lr] = av.z; As[lc+3][lr] = av.w;
        Bs[lc+0][lr] = bv.x; Bs[lc+1][lr] = bv.y; Bs[lc+2][lr] = bv.z; Bs[lc+3][lr] = bv.w;
        __syncthreads();
        #pragma unroll
        for (int kk = 0; kk < 16; kk++) {
            float a0 = As[kk][ty*4+0], a1 = As[kk][ty*4+1];
            float a2 = As[kk][ty*4+2], a3 = As[kk][ty*4+3];
            float b0 = Bs[kk][tx*4+0], b1 = Bs[kk][tx*4+1];
            float b2 = Bs[kk][tx*4+2], b3 = Bs[kk][tx*4+3];
            acc[0][0] += a0*b0; acc[0][1] += a0*b1; acc[0][2] += a0*b2; acc[0][3] += a0*b3;
            acc[1][0] += a1*b0; acc[1][1] += a1*b1; acc[1][2] += a1*b2; acc[1][3] += a1*b3;
            acc[2][0] += a2*b0; acc[2][1] += a2*b1; acc[2][2] += a2*b2; acc[2][3] += a2*b3;
            acc[3][0] += a3*b0; acc[3][1] += a3*b1; acc[3][2] += a3*b2; acc[3][3] += a3*b3;
        }
        Ap += 16; Bp += 16;
    }
    #pragma unroll
    for (int i = 0; i < 4; i++) {
        int m = m0 + ty*4 + i;
        float* crow = Cm + (size_t)m*N + n0 + tx*4;
        float4 vv;
        vv.x = acc[i][0]; vv.y = acc[i][1]; vv.z = acc[i][2]; vv.w = acc[i][3];
        if (BIAS) {
            const float* br = bias + n0 + tx*4;
            vv.x += br[0]; vv.y += br[1]; vv.z += br[2]; vv.w += br[3];
        }
        *(float4*)crow = vv;
    }
}

// ---------------- attention: one block per (window n, head) ----------------
// q[n] (64x32, scaled) vs K/V of batch (n%8): S=qk^T [64x144], softmax, O=PV [64x32]
__global__ __launch_bounds__(256) void k_attn(
    const float* __restrict__ gq, const float* __restrict__ gkv, float* __restrict__ gz)
{
    extern __shared__ float sm[];
    float* ks = sm;                   // [144][36]
    float* vs = ks + 144*36;          // [144][36]
    float* qs = vs + 144*36;          // [64][36]
    float* S  = qs + 64*36;           // [64][148]

    int n = blockIdx.x, head = blockIdx.y;
    int bb = n & 7;
    int t = threadIdx.x;

    const float* qsrc = gq + (size_t)n*(QW*CH) + head*HD;
    for (int i = t; i < QW*HD; i += 256) {
        int qi = i >> 5, d = i & 31;
        qs[qi*36 + d] = qsrc[qi*CH + d] * SCALE;
    }
    const float* kvb = gkv + (size_t)bb*(LWIN*2*CH) + head*HD;
    for (int i = t; i < LWIN*HD; i += 256) {
        int l = i >> 5, d = i & 31;
        ks[l*36 + d] = kvb[l*512 + d];
        vs[l*36 + d] = kvb[l*512 + 256 + d];
    }
    __syncthreads();

    int qi = t >> 2, g = t & 3;
    float qv[32];
    #pragma unroll
    for (int d = 0; d < 32; d++) qv[d] = qs[qi*36 + d];

    // S: each thread handles 36 key positions for its q-row
    for (int u = 0; u < 36; u++) {
        int l = g + u*4;
        const float4* kp = (const float4*)(ks + l*36);
        float acc = 0.f;
        #pragma unroll
        for (int d4 = 0; d4 < 8; d4++) {
            float4 kk = kp[d4];
            acc += qv[4*d4+0]*kk.x + qv[4*d4+1]*kk.y
                 + qv[4*d4+2]*kk.z + qv[4*d4+3]*kk.w;
        }
        S[qi*148 + l] = acc;
    }
    __syncthreads();

    // row softmax (threads 0..63, one row each)
    if (t < 64) {
        float mx = -1e30f;
        for (int l = 0; l < 144; l++) mx = fmaxf(mx, S[t*148 + l]);
        float sum = 0.f;
        for (int l = 0; l < 144; l++) { float e = __expf(S[t*148+l] - mx); S[t*148+l] = e; sum += e; }
        float inv = 1.f / sum;
        for (int l = 0; l < 144; l++) S[t*148+l] *= inv;
    }
    __syncthreads();

    // O = P @ V : thread handles (q-row, 8 head-dims)
    int d0 = (t & 3) * 8;
    float o[8] = {0,0,0,0,0,0,0,0};
    for (int l = 0; l < 144; l++) {
        float p = S[qi*148 + l];
        const float4* vp = (const float4*)(vs + l*36 + d0);
        float4 v0 = vp[0], v1 = vp[1];
        o[0] += p*v0.x; o[1] += p*v0.y; o[2] += p*v0.z; o[3] += p*v0.w;
        o[4] += p*v1.x; o[5] += p*v1.y; o[6] += p*v1.z; o[7] += p*v1.w;
    }
    // raw-reshape target: z flat = n*16384 + q*256 + head*32 + d
    float* zo = gz + (size_t)n*(QW*CH) + qi*CH + head*HD + d0;
    float4 s0, s1;
    s0.x=o[0]; s0.y=o[1]; s0.z=o[2]; s0.w=o[3];
    s1.x=o[4]; s1.y=o[5]; s1.z=o[6]; s1.w=o[7];
    *(float4*)zo = s0;
    *(float4*)(zo + 4) = s1;
}

// ---------------- depthwise 3x3 RPE, added into g_z (same BCHW flat layout) ----------------
__global__ __launch_bounds__(256) void k_rpe(
    const float* __restrict__ x, const float* __restrict__ rw, const float* __restrict__ rb)
{
    unsigned int idx = blockIdx.x*256u + threadIdx.x;     // < 18,874,368
    int w = idx % WW;
    unsigned int r = idx / WW;
    int h = r % HH; r /= HH;
    int c = r & 255;
    int b = r >> 8;

    const float* xp = x + ((size_t)b*CH + c)*HWSZ;
    const float* wp = rw + c*9;
    float acc = rb[c];
    #pragma unroll
    for (int dy = -1; dy <= 1; dy++) {
        int hh = h + dy;
        if (hh < 0 || hh >= HH) continue;
        #pragma unroll
        for (int dx = -1; dx <= 1; dx++) {
            int wc = w + dx;
            if (wc < 0 || wc >= WW) continue;
            acc += xp[hh*WW + wc] * wp[(dy+1)*3 + (dx+1)];
        }
    }
    g_z[idx] += acc;
}

// ---------------- host launch ----------------
extern "C" void kernel_launch(void* const* d_in, const int* in_sizes, int n_in,
                              void* d_out, int out_size)
{
    (void)in_sizes; (void)n_in; (void)out_size;
    const float* x      = (const float*)d_in[0];
    const float* Wq     = (const float*)d_in[1];
    const float* Wkv    = (const float*)d_in[2];
    const float* pool_w = (const float*)d_in[3];
    const float* pool_b = (const float*)d_in[4];
    const float* rpe_w  = (const float*)d_in[5];
    const float* rpe_b  = (const float*)d_in[6];
    const float* proj_w = (const float*)d_in[7];
    const float* proj_b = (const float*)d_in[8];
    float* y = (float*)d_out;

    float *p_xw, *p_q, *p_z, *p_pool, *p_pp, *p_kv, *p_pwt;
    cudaGetSymbolAddress((void**)&p_xw,  g_xw);
    cudaGetSymbolAddress((void**)&p_q,   g_q);
    cudaGetSymbolAddress((void**)&p_z,   g_z);
    cudaGetSymbolAddress((void**)&p_pool,g_pool);
    cudaGetSymbolAddress((void**)&p_pp,  g_poolpart);
    cudaGetSymbolAddress((void**)&p_kv,  g_kv);
    cudaGetSymbolAddress((void**)&p_pwt, g_poolwT);

    const int ATTN_SMEM = (144*36*2 + 64*36 + 64*148) * 4;   // 88,576 B
    cudaFuncSetAttribute(k_attn, cudaFuncAttributeMaxDynamicSharedMemorySize, ATTN_SMEM);

    // 1. window gather
    k_gather<<<dim3(NWIN, 8), 256>>>(x);
    // 2. transpose pool weights
    k_poolwT<<<dim3(CH, 2), 256>>>(pool_w);
    // 3. pool GEMM (split-K=8, deterministic partials) + reduce with bias
    k_gemm<true,  false><<<dim3(4, 18, 8), 256>>>(p_xw, p_pwt, p_pp, nullptr,
                                                  NWIN, CH, QW*CH, 2048);
    k_pool_reduce<<<NWIN, 256>>>(pool_b);
    // 4. Q projection: [73728,256] x Wq^T
    k_gemm<false, false><<<dim3(4, 1152), 256>>>(p_xw, Wq, p_q, nullptr,
                                                 NWIN*QW, CH, CH, CH);
    // 5. KV projection on pooled tokens: [1152,256] x Wkv^T -> [1152,512]
    k_gemm<false, false><<<dim3(8, 18), 256>>>(p_pool, Wkv, p_kv, nullptr,
                                               NWIN, 2*CH, CH, CH);
    // 6. attention per (window, head), writes g_z (full coverage)
    k_attn<<<dim3(NWIN, NHEAD), 256, ATTN_SMEM>>>(p_q, p_kv, p_z);
    // 7. RPE depthwise conv, accumulate into g_z
    k_rpe<<<(NWIN*QW*CH)/256, 256>>>(x, rpe_w, rpe_b);
    // 8. output projection with bias -> d_out
    k_gemm<false, true><<<dim3(4, 1152), 256>>>(p_z, proj_w, y, proj_b,
                                                NWIN*QW, CH, CH, CH);
}

// round 9
// speedup vs baseline: 1.0002x; 1.0002x over previous
#include <cuda_runtime.h>
#include <cuda_bf16.h>

// ---------------- problem constants ----------------
#define BATCH 8
#define CH    256
#define HH    96
#define WW    96
#define HWSZ  (HH*WW)        // 9216
#define NWD   12             // windows per spatial dim
#define LWIN  144            // windows per image
#define NWIN  1152           // total windows (BATCH*LWIN)
#define QW    64             // queries per window (8x8)
#define NHEAD 8
#define HD    32
#define SCALE 0.1767766952966369f   // 32^-0.5

#define XW_ELEMS ((size_t)NWIN*QW*CH)   // 18,874,368

// ---------------- device scratch (no allocs allowed) ----------------
__device__ float g_xw[NWIN*QW*CH];        // [n][s][c]  window-gathered x
__device__ float g_q [NWIN*QW*CH];        // [n][s][o]  Q projection
__device__ float g_z [NWIN*QW*CH];        // attn out + rpe, BCHW-flat
__device__ float g_pool[NWIN*CH];         // pooled tokens [bl][c]
__device__ float g_poolpart[8*NWIN*CH];   // split-K partials
__device__ float g_kv[NWIN*2*CH];         // [bl][t*256 + head*32 + d]
__device__ float g_poolwT[CH*QW*CH];      // pool_w transposed to [o][s*256+c]

// ---------------- window gather: x(BCHW) -> g_xw[n][s][c] ----------------
__global__ __launch_bounds__(256) void k_gather(const float* __restrict__ x)
{
    __shared__ float tile[64][33];
    int n  = blockIdx.x;
    int ct = blockIdx.y;            // channel tile of 32
    int b  = n / LWIN;
    int wi = n % LWIN;
    int wh = wi / NWD, wwi = wi % NWD;
    int t = threadIdx.x;

    // load 32 channels x 64 window pixels; 8-consecutive-float reads (full 32B sectors)
    int c_loc = t >> 3;             // 0..31
    int j     = t & 7;              // 0..7
    const float* xb = x + ((size_t)b*CH + ct*32 + c_loc)*HWSZ + (wh*8)*WW + wwi*8 + j;
    #pragma unroll
    for (int i = 0; i < 8; i++)
        tile[i*8 + j][c_loc] = xb[i*WW];
    __syncthreads();

    // store coalesced over channels
    int c2 = t & 31;
    float* out = g_xw + (size_t)n*(QW*CH) + ct*32 + c2;
    #pragma unroll
    for (int it = 0; it < 8; it++) {
        int s = (t >> 5) + it*8;
        out[s*CH] = tile[s][c2];
    }
}

// ---------------- pool_w[o][c][s] -> g_poolwT[o][s*256+c] ----------------
__global__ __launch_bounds__(256) void k_poolwT(const float* __restrict__ pw)
{
    __shared__ float sm[128*65];
    int o  = blockIdx.x;
    int c0 = blockIdx.y * 128;
    int t  = threadIdx.x;
    const float* p = pw + (size_t)o*16384 + (size_t)c0*64;
    #pragma unroll 4
    for (int i = 0; i < 32; i++) {
        int idx = i*256 + t;
        int c = idx >> 6, s = idx & 63;
        sm[c*65 + s] = p[idx];
    }
    __syncthreads();
    float* out = g_poolwT + (size_t)o*16384 + c0;
    #pragma unroll 4
    for (int i = 0; i < 32; i++) {
        int idx = i*256 + t;
        int s = idx >> 7, c = idx & 127;
        out[s*256 + c] = sm[c*65 + s];
    }
}

// ---------------- split-K reduce for pool (+bias) ----------------
__global__ __launch_bounds__(256) void k_pool_reduce(const float* __restrict__ pb)
{
    int idx = blockIdx.x*256 + threadIdx.x;     // NWIN*CH
    float a = pb[idx & 255];
    #pragma unroll
    for (int z = 0; z < 8; z++)
        a += g_poolpart[(size_t)z*(NWIN*CH) + idx];
    g_pool[idx] = a;
}

// ---------------- tiled NT SGEMM: C[m,n] = sum_k A[m*K+k]*B[n*K+k] ----------------
// 64x64 tile, BK=16, 256 threads, 4x4 microtile. lda=ldb=K, ldc=N (exact tiles).
template<bool SPLIT, bool BIAS>
__global__ __launch_bounds__(256) void k_gemm(
    const float* __restrict__ A, const float* __restrict__ Bm,
    float* __restrict__ Cm, const float* __restrict__ bias,
    int M, int N, int K, int kcount)
{
    __shared__ float As[16][68];
    __shared__ float Bs[16][68];
    const int m0 = blockIdx.y * 64;
    const int n0 = blockIdx.x * 64;
    int k0 = 0;
    if (SPLIT) { k0 = blockIdx.z * kcount; Cm += (size_t)blockIdx.z * M * N; }
    const int tid = threadIdx.x;
    const int tx = tid & 15, ty = tid >> 4;
    const int lr = tid >> 2;           // 0..63 tile row
    const int lc = (tid & 3) * 4;      // k offset 0,4,8,12

    const float* Ap = A + (size_t)(m0 + lr)*K + k0 + lc;
    const float* Bp = Bm + (size_t)(n0 + lr)*K + k0 + lc;

    float acc[4][4] = {};
    for (int kt = 0; kt < kcount; kt += 16) {
        float4 av = *(const float4*)Ap;
        float4 bv = *(const float4*)Bp;
        __syncthreads();
        As[lc+0][lr] = av.x; As[lc+1][lr] = av.y; As[lc+2][lr] = av.z; As[lc+3][lr] = av.w;
        Bs[lc+0][lr] = bv.x; Bs[lc+1][lr] = bv.y; Bs[lc+2][lr] = bv.z; Bs[lc+3][lr] = bv.w;
        __syncthreads();
        #pragma unroll
        for (int kk = 0; kk < 16; kk++) {
            float a0 = As[kk][ty*4+0], a1 = As[kk][ty*4+1];
            float a2 = As[kk][ty*4+2], a3 = As[kk][ty*4+3];
            float b0 = Bs[kk][tx*4+0], b1 = Bs[kk][tx*4+1];
            float b2 = Bs[kk][tx*4+2], b3 = Bs[kk][tx*4+3];
            acc[0][0] += a0*b0; acc[0][1] += a0*b1; acc[0][2] += a0*b2; acc[0][3] += a0*b3;
            acc[1][0] += a1*b0; acc[1][1] += a1*b1; acc[1][2] += a1*b2; acc[1][3] += a1*b3;
            acc[2][0] += a2*b0; acc[2][1] += a2*b1; acc[2][2] += a2*b2; acc[2][3] += a2*b3;
            acc[3][0] += a3*b0; acc[3][1] += a3*b1; acc[3][2] += a3*b2; acc[3][3] += a3*b3;
        }
        Ap += 16; Bp += 16;
    }
    #pragma unroll
    for (int i = 0; i < 4; i++) {
        int m = m0 + ty*4 + i;
        float* crow = Cm + (size_t)m*N + n0 + tx*4;
        float4 vv;
        vv.x = acc[i][0]; vv.y = acc[i][1]; vv.z = acc[i][2]; vv.w = acc[i][3];
        if (BIAS) {
            const float* br = bias + n0 + tx*4;
            vv.x += br[0]; vv.y += br[1]; vv.z += br[2]; vv.w += br[3];
        }
        *(float4*)crow = vv;
    }
}

// ---------------- attention: one block per (window n, head) ----------------
// q[n] (64x32, scaled) vs K/V of batch (n%8): S=qk^T [64x144], softmax, O=PV [64x32]
__global__ __launch_bounds__(256) void k_attn(
    const float* __restrict__ gq, const float* __restrict__ gkv, float* __restrict__ gz)
{
    extern __shared__ float sm[];
    float* ks = sm;                   // [144][36]
    float* vs = ks + 144*36;          // [144][36]
    float* qs = vs + 144*36;          // [64][36]
    float* S  = qs + 64*36;           // [64][148]

    int n = blockIdx.x, head = blockIdx.y;
    int bb = n & 7;
    int t = threadIdx.x;

    const float* qsrc = gq + (size_t)n*(QW*CH) + head*HD;
    for (int i = t; i < QW*HD; i += 256) {
        int qi = i >> 5, d = i & 31;
        qs[qi*36 + d] = qsrc[qi*CH + d] * SCALE;
    }
    const float* kvb = gkv + (size_t)bb*(LWIN*2*CH) + head*HD;
    for (int i = t; i < LWIN*HD; i += 256) {
        int l = i >> 5, d = i & 31;
        ks[l*36 + d] = kvb[l*512 + d];
        vs[l*36 + d] = kvb[l*512 + 256 + d];
    }
    __syncthreads();

    int qi = t >> 2, g = t & 3;
    float qv[32];
    #pragma unroll
    for (int d = 0; d < 32; d++) qv[d] = qs[qi*36 + d];

    // S: each thread handles 36 key positions for its q-row
    for (int u = 0; u < 36; u++) {
        int l = g + u*4;
        const float4* kp = (const float4*)(ks + l*36);
        float acc = 0.f;
        #pragma unroll
        for (int d4 = 0; d4 < 8; d4++) {
            float4 kk = kp[d4];
            acc += qv[4*d4+0]*kk.x + qv[4*d4+1]*kk.y
                 + qv[4*d4+2]*kk.z + qv[4*d4+3]*kk.w;
        }
        S[qi*148 + l] = acc;
    }
    __syncthreads();

    // row softmax (threads 0..63, one row each)
    if (t < 64) {
        float mx = -1e30f;
        for (int l = 0; l < 144; l++) mx = fmaxf(mx, S[t*148 + l]);
        float sum = 0.f;
        for (int l = 0; l < 144; l++) { float e = __expf(S[t*148+l] - mx); S[t*148+l] = e; sum += e; }
        float inv = 1.f / sum;
        for (int l = 0; l < 144; l++) S[t*148+l] *= inv;
    }
    __syncthreads();

    // O = P @ V : thread handles (q-row, 8 head-dims)
    int d0 = (t & 3) * 8;
    float o[8] = {0,0,0,0,0,0,0,0};
    for (int l = 0; l < 144; l++) {
        float p = S[qi*148 + l];
        const float4* vp = (const float4*)(vs + l*36 + d0);
        float4 v0 = vp[0], v1 = vp[1];
        o[0] += p*v0.x; o[1] += p*v0.y; o[2] += p*v0.z; o[3] += p*v0.w;
        o[4] += p*v1.x; o[5] += p*v1.y; o[6] += p*v1.z; o[7] += p*v1.w;
    }
    // raw-reshape target: z flat = n*16384 + q*256 + head*32 + d
    float* zo = gz + (size_t)n*(QW*CH) + qi*CH + head*HD + d0;
    float4 s0, s1;
    s0.x=o[0]; s0.y=o[1]; s0.z=o[2]; s0.w=o[3];
    s1.x=o[4]; s1.y=o[5]; s1.z=o[6]; s1.w=o[7];
    *(float4*)zo = s0;
    *(float4*)(zo + 4) = s1;
}

// ---------------- depthwise 3x3 RPE, added into g_z (same BCHW flat layout) ----------------
__global__ __launch_bounds__(256) void k_rpe(
    const float* __restrict__ x, const float* __restrict__ rw, const float* __restrict__ rb)
{
    unsigned int idx = blockIdx.x*256u + threadIdx.x;     // < 18,874,368
    int w = idx % WW;
    unsigned int r = idx / WW;
    int h = r % HH; r /= HH;
    int c = r & 255;
    int b = r >> 8;

    const float* xp = x + ((size_t)b*CH + c)*HWSZ;
    const float* wp = rw + c*9;
    float acc = rb[c];
    #pragma unroll
    for (int dy = -1; dy <= 1; dy++) {
        int hh = h + dy;
        if (hh < 0 || hh >= HH) continue;
        #pragma unroll
        for (int dx = -1; dx <= 1; dx++) {
            int wc = w + dx;
            if (wc < 0 || wc >= WW) continue;
            acc += xp[hh*WW + wc] * wp[(dy+1)*3 + (dx+1)];
        }
    }
    g_z[idx] += acc;
}

// ---------------- host launch ----------------
extern "C" void kernel_launch(void* const* d_in, const int* in_sizes, int n_in,
                              void* d_out, int out_size)
{
    (void)in_sizes; (void)n_in; (void)out_size;
    const float* x      = (const float*)d_in[0];
    const float* Wq     = (const float*)d_in[1];
    const float* Wkv    = (const float*)d_in[2];
    const float* pool_w = (const float*)d_in[3];
    const float* pool_b = (const float*)d_in[4];
    const float* rpe_w  = (const float*)d_in[5];
    const float* rpe_b  = (const float*)d_in[6];
    const float* proj_w = (const float*)d_in[7];
    const float* proj_b = (const float*)d_in[8];
    float* y = (float*)d_out;

    float *p_xw, *p_q, *p_z, *p_pool, *p_pp, *p_kv, *p_pwt;
    cudaGetSymbolAddress((void**)&p_xw,  g_xw);
    cudaGetSymbolAddress((void**)&p_q,   g_q);
    cudaGetSymbolAddress((void**)&p_z,   g_z);
    cudaGetSymbolAddress((void**)&p_pool,g_pool);
    cudaGetSymbolAddress((void**)&p_pp,  g_poolpart);
    cudaGetSymbolAddress((void**)&p_kv,  g_kv);
    cudaGetSymbolAddress((void**)&p_pwt, g_poolwT);

    const int ATTN_SMEM = (144*36*2 + 64*36 + 64*148) * 4;   // 88,576 B
    cudaFuncSetAttribute(k_attn, cudaFuncAttributeMaxDynamicSharedMemorySize, ATTN_SMEM);

    // 1. window gather
    k_gather<<<dim3(NWIN, 8), 256>>>(x);
    // 2. transpose pool weights
    k_poolwT<<<dim3(CH, 2), 256>>>(pool_w);
    // 3. pool GEMM (split-K=8, deterministic partials) + reduce with bias
    k_gemm<true,  false><<<dim3(4, 18, 8), 256>>>(p_xw, p_pwt, p_pp, nullptr,
                                                  NWIN, CH, QW*CH, 2048);
    k_pool_reduce<<<NWIN, 256>>>(pool_b);
    // 4. Q projection: [73728,256] x Wq^T
    k_gemm<false, false><<<dim3(4, 1152), 256>>>(p_xw, Wq, p_q, nullptr,
                                                 NWIN*QW, CH, CH, CH);
    // 5. KV projection on pooled tokens: [1152,256] x Wkv^T -> [1152,512]
    k_gemm<false, false><<<dim3(8, 18), 256>>>(p_pool, Wkv, p_kv, nullptr,
                                               NWIN, 2*CH, CH, CH);
    // 6. attention per (window, head), writes g_z (full coverage)
    k_attn<<<dim3(NWIN, NHEAD), 256, ATTN_SMEM>>>(p_q, p_kv, p_z);
    // 7. RPE depthwise conv, accumulate into g_z
    k_rpe<<<(NWIN*QW*CH)/256, 256>>>(x, rpe_w, rpe_b);
    // 8. output projection with bias -> d_out
    k_gemm<false, true><<<dim3(4, 1152), 256>>>(p_z, proj_w, y, proj_b,
                                                NWIN*QW, CH, CH, CH);
}

// round 12
// speedup vs baseline: 1.4532x; 1.4528x over previous
#include <cuda_runtime.h>
#include <cuda_bf16.h>
#include <cstdint>

// ---------------- problem constants ----------------
#define BATCH 8
#define CH    256
#define HH    96
#define WW    96
#define HWSZ  (HH*WW)        // 9216
#define NWD   12
#define LWIN  144
#define NWIN  1152
#define QW    64
#define NHEAD 8
#define HD    32
#define SCALE 0.1767766952966369f

// ---------------- device scratch ----------------
__device__ float g_xw[NWIN*QW*CH];         // [n][s][c]
__device__ float g_q [NWIN*QW*CH];         // Q projection
__device__ float g_z [NWIN*QW*CH];         // attn out + rpe (BCHW-flat)
__device__ float g_pool[NWIN*CH];          // pooled tokens
__device__ float g_poolpart[32*NWIN*CH];   // split-K partials (32 slices)
__device__ float g_kv[NWIN*2*CH];          // [bl][t*256 + head*32 + d]
__device__ float g_poolwT[CH*QW*CH];       // pool_w -> [o][s*256+c]

// ---------------- helpers ----------------
__device__ __forceinline__ uint32_t smem_u32(const void* p) {
    uint32_t a;
    asm("{ .reg .u64 t; cvta.to.shared.u64 t, %1; cvt.u32.u64 %0, t; }" : "=r"(a) : "l"(p));
    return a;
}
__device__ __forceinline__ void ldsm4(uint32_t* r, uint32_t addr) {
    asm volatile("ldmatrix.sync.aligned.m8n8.x4.shared.b16 {%0,%1,%2,%3}, [%4];"
        : "=r"(r[0]), "=r"(r[1]), "=r"(r[2]), "=r"(r[3]) : "r"(addr));
}
__device__ __forceinline__ void mma16816(float* c, const uint32_t* a, const uint32_t* b) {
    asm volatile("mma.sync.aligned.m16n8k16.row.col.f32.bf16.bf16.f32 "
        "{%0,%1,%2,%3}, {%4,%5,%6,%7}, {%8,%9}, {%0,%1,%2,%3};"
        : "+f"(c[0]), "+f"(c[1]), "+f"(c[2]), "+f"(c[3])
        : "r"(a[0]), "r"(a[1]), "r"(a[2]), "r"(a[3]), "r"(b[0]), "r"(b[1]));
}
__device__ __forceinline__ void cvt_hl(float4 v, uint2& h, uint2& l) {
    __nv_bfloat16 h0 = __float2bfloat16(v.x), h1 = __float2bfloat16(v.y);
    __nv_bfloat16 h2 = __float2bfloat16(v.z), h3 = __float2bfloat16(v.w);
    __nv_bfloat16 l0 = __float2bfloat16(v.x - __bfloat162float(h0));
    __nv_bfloat16 l1 = __float2bfloat16(v.y - __bfloat162float(h1));
    __nv_bfloat16 l2 = __float2bfloat16(v.z - __bfloat162float(h2));
    __nv_bfloat16 l3 = __float2bfloat16(v.w - __bfloat162float(h3));
    h.x = ((uint32_t)__bfloat16_as_ushort(h1) << 16) | __bfloat16_as_ushort(h0);
    h.y = ((uint32_t)__bfloat16_as_ushort(h3) << 16) | __bfloat16_as_ushort(h2);
    l.x = ((uint32_t)__bfloat16_as_ushort(l1) << 16) | __bfloat16_as_ushort(l0);
    l.y = ((uint32_t)__bfloat16_as_ushort(l3) << 16) | __bfloat16_as_ushort(l2);
}

// =============== HMMA NT GEMM (3-pass bf16 hi/lo, fp32-class accuracy) ===============
// C[m,n] = sum_k A[m*K+k] * B[n*K+k].  Block tile 128x128, BK=32, 8 warps (2x4),
// warp tile 64x32 via m16n8k16. grid = (N/128, M/128, splitK).
__global__ __launch_bounds__(256) void k_gemm_mma(
    const float* __restrict__ A, const float* __restrict__ B,
    float* __restrict__ C, const float* __restrict__ bias,
    int M, int K, int ldc, int kcount)
{
    __shared__ __align__(16) __nv_bfloat16 AsH[128][40];
    __shared__ __align__(16) __nv_bfloat16 AsL[128][40];
    __shared__ __align__(16) __nv_bfloat16 BsH[128][40];
    __shared__ __align__(16) __nv_bfloat16 BsL[128][40];

    const int t    = threadIdx.x;
    const int lane = t & 31;
    const int wid  = t >> 5;
    const int n0 = blockIdx.x * 128;
    const int m0 = blockIdx.y * 128;
    const int k0 = blockIdx.z * kcount;
    A += (size_t)m0 * K + k0;
    B += (size_t)n0 * K + k0;
    C += (size_t)blockIdx.z * M * ldc + (size_t)m0 * ldc + n0;
    const float* bp = bias ? bias + n0 : nullptr;

    const int wm = (wid >> 2) * 64;   // warp row offset: 0 / 64
    const int wn = (wid & 3) * 32;    // warp col offset: 0/32/64/96

    const uint32_t aH_base = smem_u32(AsH), aL_base = smem_u32(AsL);
    const uint32_t bH_base = smem_u32(BsH), bL_base = smem_u32(BsL);

    float acc[4][4][4] = {};

    const int rb = t >> 3;        // 0..31 row base
    const int jb = t & 7;         // float4 column group

    const int nChunks = kcount >> 5;
    for (int c = 0; c < nChunks; c++) {
        const float* Ag = A + c * 32;
        const float* Bg = B + c * 32;
        // ---- global -> smem with fp32 -> (hi, lo) bf16 split ----
        #pragma unroll
        for (int it = 0; it < 4; it++) {
            int r = it * 32 + rb;
            float4 va = *(const float4*)(Ag + (size_t)r * K + jb * 4);
            float4 vb = *(const float4*)(Bg + (size_t)r * K + jb * 4);
            uint2 h, l;
            cvt_hl(va, h, l);
            *(uint2*)((char*)AsH + r * 80 + jb * 8) = h;
            *(uint2*)((char*)AsL + r * 80 + jb * 8) = l;
            cvt_hl(vb, h, l);
            *(uint2*)((char*)BsH + r * 80 + jb * 8) = h;
            *(uint2*)((char*)BsL + r * 80 + jb * 8) = l;
        }
        __syncthreads();

        #pragma unroll
        for (int kk = 0; kk < 32; kk += 16) {
            uint32_t aH[4][4], aL[4][4], bH[2][4], bL[2][4];
            // A fragments: 4 m-tiles (16 rows each)
            #pragma unroll
            for (int mi = 0; mi < 4; mi++) {
                uint32_t off = (uint32_t)((wm + mi * 16 + (lane & 15)) * 80
                                          + (kk + ((lane >> 4) << 3)) * 2);
                ldsm4(aH[mi], aH_base + off);
                ldsm4(aL[mi], aL_base + off);
            }
            // B fragments: 2 ldsm.x4 cover 4 n8-tiles (32 cols)
            #pragma unroll
            for (int nj = 0; nj < 2; nj++) {
                uint32_t off = (uint32_t)((wn + nj * 16 + ((lane >> 4) << 3) + (lane & 7)) * 80
                                          + (kk + (((lane >> 3) & 1) << 3)) * 2);
                ldsm4(bH[nj], bH_base + off);
                ldsm4(bL[nj], bL_base + off);
            }
            #pragma unroll
            for (int mi = 0; mi < 4; mi++)
                #pragma unroll
                for (int ni = 0; ni < 4; ni++) {
                    const uint32_t* bh = &bH[ni >> 1][(ni & 1) * 2];
                    const uint32_t* bl = &bL[ni >> 1][(ni & 1) * 2];
                    mma16816(acc[mi][ni], aH[mi], bh);
                    mma16816(acc[mi][ni], aH[mi], bl);
                    mma16816(acc[mi][ni], aL[mi], bh);
                }
        }
        __syncthreads();
    }

    // ---- epilogue ----
    #pragma unroll
    for (int mi = 0; mi < 4; mi++)
        #pragma unroll
        for (int ni = 0; ni < 4; ni++) {
            int r0 = wm + mi * 16 + (lane >> 2);
            int cc = wn + ni * 8 + (lane & 3) * 2;
            float b0 = 0.f, b1 = 0.f;
            if (bp) { b0 = bp[cc]; b1 = bp[cc + 1]; }
            float2 v0 = make_float2(acc[mi][ni][0] + b0, acc[mi][ni][1] + b1);
            float2 v1 = make_float2(acc[mi][ni][2] + b0, acc[mi][ni][3] + b1);
            *(float2*)(C + (size_t)r0 * ldc + cc) = v0;
            *(float2*)(C + (size_t)(r0 + 8) * ldc + cc) = v1;
        }
}

// ---------------- window gather: x(BCHW) -> g_xw[n][s][c] ----------------
__global__ __launch_bounds__(256) void k_gather(const float* __restrict__ x)
{
    __shared__ float tile[64][33];
    int n  = blockIdx.x;
    int ct = blockIdx.y;
    int b  = n / LWIN;
    int wi = n % LWIN;
    int wh = wi / NWD, wwi = wi % NWD;
    int t = threadIdx.x;

    int c_loc = t >> 3;
    int j     = t & 7;
    const float* xb = x + ((size_t)b*CH + ct*32 + c_loc)*HWSZ + (wh*8)*WW + wwi*8 + j;
    #pragma unroll
    for (int i = 0; i < 8; i++)
        tile[i*8 + j][c_loc] = xb[i*WW];
    __syncthreads();

    int c2 = t & 31;
    float* out = g_xw + (size_t)n*(QW*CH) + ct*32 + c2;
    #pragma unroll
    for (int it = 0; it < 8; it++) {
        int s = (t >> 5) + it*8;
        out[s*CH] = tile[s][c2];
    }
}

// ---------------- pool_w[o][c][s] -> g_poolwT[o][s*256+c] ----------------
__global__ __launch_bounds__(256) void k_poolwT(const float* __restrict__ pw)
{
    __shared__ float sm[128*65];
    int o  = blockIdx.x;
    int c0 = blockIdx.y * 128;
    int t  = threadIdx.x;
    const float* p = pw + (size_t)o*16384 + (size_t)c0*64;
    #pragma unroll 4
    for (int i = 0; i < 32; i++) {
        int idx = i*256 + t;
        int c = idx >> 6, s = idx & 63;
        sm[c*65 + s] = p[idx];
    }
    __syncthreads();
    float* out = g_poolwT + (size_t)o*16384 + c0;
    #pragma unroll 4
    for (int i = 0; i < 32; i++) {
        int idx = i*256 + t;
        int s = idx >> 7, c = idx & 127;
        out[s*256 + c] = sm[c*65 + s];
    }
}

// ---------------- split-K reduce for pool (+bias), 32 slices ----------------
__global__ __launch_bounds__(256) void k_pool_reduce(const float* __restrict__ pb)
{
    int idx = blockIdx.x*256 + threadIdx.x;
    float a = pb[idx & 255];
    #pragma unroll
    for (int z = 0; z < 32; z++)
        a += g_poolpart[(size_t)z*(NWIN*CH) + idx];
    g_pool[idx] = a;
}

// ---------------- attention: one block per (window n, head) ----------------
__global__ __launch_bounds__(256) void k_attn(
    const float* __restrict__ gq, const float* __restrict__ gkv, float* __restrict__ gz)
{
    extern __shared__ float sm[];
    float* ks = sm;                   // [144][36]
    float* vs = ks + 144*36;          // [144][36]
    float* qs = vs + 144*36;          // [64][36]
    float* S  = qs + 64*36;           // [64][148]

    int n = blockIdx.x, head = blockIdx.y;
    int bb = n & 7;
    int t = threadIdx.x;

    const float* qsrc = gq + (size_t)n*(QW*CH) + head*HD;
    for (int i = t; i < QW*HD; i += 256) {
        int qi = i >> 5, d = i & 31;
        qs[qi*36 + d] = qsrc[qi*CH + d] * SCALE;
    }
    const float* kvb = gkv + (size_t)bb*(LWIN*2*CH) + head*HD;
    for (int i = t; i < LWIN*HD; i += 256) {
        int l = i >> 5, d = i & 31;
        ks[l*36 + d] = kvb[l*512 + d];
        vs[l*36 + d] = kvb[l*512 + 256 + d];
    }
    __syncthreads();

    int qi = t >> 2, g = t & 3;
    float qv[32];
    #pragma unroll
    for (int d = 0; d < 32; d++) qv[d] = qs[qi*36 + d];

    for (int u = 0; u < 36; u++) {
        int l = g + u*4;
        const float4* kp = (const float4*)(ks + l*36);
        float acc = 0.f;
        #pragma unroll
        for (int d4 = 0; d4 < 8; d4++) {
            float4 kk = kp[d4];
            acc += qv[4*d4+0]*kk.x + qv[4*d4+1]*kk.y
                 + qv[4*d4+2]*kk.z + qv[4*d4+3]*kk.w;
        }
        S[qi*148 + l] = acc;
    }
    __syncthreads();

    if (t < 64) {
        float mx = -1e30f;
        for (int l = 0; l < 144; l++) mx = fmaxf(mx, S[t*148 + l]);
        float sum = 0.f;
        for (int l = 0; l < 144; l++) { float e = __expf(S[t*148+l] - mx); S[t*148+l] = e; sum += e; }
        float inv = 1.f / sum;
        for (int l = 0; l < 144; l++) S[t*148+l] *= inv;
    }
    __syncthreads();

    int d0 = (t & 3) * 8;
    float o[8] = {0,0,0,0,0,0,0,0};
    for (int l = 0; l < 144; l++) {
        float p = S[qi*148 + l];
        const float4* vp = (const float4*)(vs + l*36 + d0);
        float4 v0 = vp[0], v1 = vp[1];
        o[0] += p*v0.x; o[1] += p*v0.y; o[2] += p*v0.z; o[3] += p*v0.w;
        o[4] += p*v1.x; o[5] += p*v1.y; o[6] += p*v1.z; o[7] += p*v1.w;
    }
    float* zo = gz + (size_t)n*(QW*CH) + qi*CH + head*HD + d0;
    float4 s0, s1;
    s0.x=o[0]; s0.y=o[1]; s0.z=o[2]; s0.w=o[3];
    s1.x=o[4]; s1.y=o[5]; s1.z=o[6]; s1.w=o[7];
    *(float4*)zo = s0;
    *(float4*)(zo + 4) = s1;
}

// ---------------- depthwise 3x3 RPE, added into g_z ----------------
__global__ __launch_bounds__(256) void k_rpe(
    const float* __restrict__ x, const float* __restrict__ rw, const float* __restrict__ rb)
{
    unsigned int idx = blockIdx.x*256u + threadIdx.x;
    int w = idx % WW;
    unsigned int r = idx / WW;
    int h = r % HH; r /= HH;
    int c = r & 255;
    int b = r >> 8;

    const float* xp = x + ((size_t)b*CH + c)*HWSZ;
    const float* wp = rw + c*9;
    float acc = rb[c];
    #pragma unroll
    for (int dy = -1; dy <= 1; dy++) {
        int hh = h + dy;
        if (hh < 0 || hh >= HH) continue;
        #pragma unroll
        for (int dx = -1; dx <= 1; dx++) {
            int wc = w + dx;
            if (wc < 0 || wc >= WW) continue;
            acc += xp[hh*WW + wc] * wp[(dy+1)*3 + (dx+1)];
        }
    }
    g_z[idx] += acc;
}

// ---------------- host launch ----------------
extern "C" void kernel_launch(void* const* d_in, const int* in_sizes, int n_in,
                              void* d_out, int out_size)
{
    (void)in_sizes; (void)n_in; (void)out_size;
    const float* x      = (const float*)d_in[0];
    const float* Wq     = (const float*)d_in[1];
    const float* Wkv    = (const float*)d_in[2];
    const float* pool_w = (const float*)d_in[3];
    const float* pool_b = (const float*)d_in[4];
    const float* rpe_w  = (const float*)d_in[5];
    const float* rpe_b  = (const float*)d_in[6];
    const float* proj_w = (const float*)d_in[7];
    const float* proj_b = (const float*)d_in[8];
    float* y = (float*)d_out;

    float *p_xw, *p_q, *p_z, *p_pool, *p_pp, *p_kv, *p_pwt;
    cudaGetSymbolAddress((void**)&p_xw,  g_xw);
    cudaGetSymbolAddress((void**)&p_q,   g_q);
    cudaGetSymbolAddress((void**)&p_z,   g_z);
    cudaGetSymbolAddress((void**)&p_pool,g_pool);
    cudaGetSymbolAddress((void**)&p_pp,  g_poolpart);
    cudaGetSymbolAddress((void**)&p_kv,  g_kv);
    cudaGetSymbolAddress((void**)&p_pwt, g_poolwT);

    const int ATTN_SMEM = (144*36*2 + 64*36 + 64*148) * 4;   // 88,576 B
    cudaFuncSetAttribute(k_attn, cudaFuncAttributeMaxDynamicSharedMemorySize, ATTN_SMEM);

    // 1. window gather
    k_gather<<<dim3(NWIN, 8), 256>>>(x);
    // 2. transpose pool weights
    k_poolwT<<<dim3(CH, 2), 256>>>(pool_w);
    // 3. pool GEMM: [1152,16384] x poolwT^T, split-K=32 -> partials, then reduce+bias
    k_gemm_mma<<<dim3(2, 9, 32), 256>>>(p_xw, p_pwt, p_pp, nullptr,
                                        NWIN, QW*CH, CH, 512);
    k_pool_reduce<<<NWIN, 256>>>(pool_b);
    // 4. Q projection: [73728,256] x Wq^T
    k_gemm_mma<<<dim3(2, 576, 1), 256>>>(p_xw, Wq, p_q, nullptr,
                                         NWIN*QW, CH, CH, CH);
    // 5. KV projection: [1152,256] x Wkv^T -> [1152,512]
    k_gemm_mma<<<dim3(4, 9, 1), 256>>>(p_pool, Wkv, p_kv, nullptr,
                                       NWIN, CH, 2*CH, CH);
    // 6. attention per (window, head) -> g_z
    k_attn<<<dim3(NWIN, NHEAD), 256, ATTN_SMEM>>>(p_q, p_kv, p_z);
    // 7. RPE depthwise conv accumulate into g_z
    k_rpe<<<(NWIN*QW*CH)/256, 256>>>(x, rpe_w, rpe_b);
    // 8. output projection + bias -> d_out
    k_gemm_mma<<<dim3(2, 576, 1), 256>>>(p_z, proj_w, y, proj_b,
                                         NWIN*QW, CH, CH, CH);
}